// round 15
// baseline (speedup 1.0000x reference)
#include <cuda_runtime.h>
#include <stdint.h>

#define N_NODES   100000
#define N_EDGES   1600000
#define D         128
#define N_LAYERS  3
#define N_CLASSES 10
#define N_GRAPHS  512
#define BN_EPS    1e-5f

// ---------------------------------------------------------------------------
// Static device scratch (zero-init at load; kernels re-zero what they dirty)
// ---------------------------------------------------------------------------
__device__ float g_bufA[(size_t)N_NODES * D];
__device__ float g_bufB[(size_t)N_NODES * D];
__device__ int   g_deg[N_NODES];
__device__ int   g_off[N_NODES + 1];
__device__ int   g_cur[N_NODES];
__device__ int   g_csr[N_EDGES];
__device__ float g_sum[D];
__device__ float g_sumsq[D];
__device__ float g_scale[D];
__device__ float g_shift[D];
__device__ float g_pool[N_GRAPHS * D];
__device__ float g_cnt[N_GRAPHS];

// ---------------------------------------------------------------------------
// Packed f32x2 helpers
// ---------------------------------------------------------------------------
__device__ __forceinline__ unsigned long long ffma2(unsigned long long a,
                                                    unsigned long long b,
                                                    unsigned long long c) {
    unsigned long long d;
    asm("fma.rn.f32x2 %0, %1, %2, %3;" : "=l"(d) : "l"(a), "l"(b), "l"(c));
    return d;
}
__device__ __forceinline__ void unpack2(unsigned long long v, float& lo, float& hi) {
    unsigned int a, b;
    asm("mov.b64 {%0, %1}, %2;" : "=r"(a), "=r"(b) : "l"(v));
    lo = __uint_as_float(a);
    hi = __uint_as_float(b);
}
__device__ __forceinline__ unsigned long long pack2(float x) {
    unsigned long long r;
    unsigned int u = __float_as_uint(x);
    asm("mov.b64 %0, {%1, %1};" : "=l"(r) : "r"(u));
    return r;
}

// ---------------------------------------------------------------------------
// CSR build (g_deg zero on entry; scan self-cleans it)
// ---------------------------------------------------------------------------
__global__ void hist_kernel(const int* __restrict__ dstA) {
    for (int e = blockIdx.x * blockDim.x + threadIdx.x; e < N_EDGES;
         e += gridDim.x * blockDim.x)
        atomicAdd(&g_deg[dstA[e]], 1);
}

__global__ void scan_kernel() {
    const int T = 1024;
    const int chunk = (N_NODES + T - 1) / T;
    int tid = threadIdx.x;
    int lo = tid * chunk, hi = lo + chunk;
    if (hi > N_NODES) hi = N_NODES;
    if (lo > N_NODES) lo = N_NODES;
    int s = 0;
    for (int i = lo; i < hi; i++) s += g_deg[i];
    __shared__ int sm[T];
    sm[tid] = s;
    __syncthreads();
    for (int off = 1; off < T; off <<= 1) {
        int v = (tid >= off) ? sm[tid - off] : 0;
        __syncthreads();
        sm[tid] += v;
        __syncthreads();
    }
    int run = (tid == 0) ? 0 : sm[tid - 1];
    for (int i = lo; i < hi; i++) {
        int d = g_deg[i];
        g_off[i] = run;
        g_cur[i] = run;
        run += d;
        g_deg[i] = 0;
    }
    if (tid == T - 1) g_off[N_NODES] = run;
    if (tid < D) {
        g_scale[tid] = 1.0f;
        g_shift[tid] = 0.0f;
        g_sum[tid]   = 0.0f;
        g_sumsq[tid] = 0.0f;
    }
    for (int i = tid; i < N_GRAPHS * D; i += T) g_pool[i] = 0.0f;
    for (int i = tid; i < N_GRAPHS; i += T)     g_cnt[i]  = 0.0f;
}

__global__ void fill_kernel(const int* __restrict__ srcA,
                            const int* __restrict__ dstA) {
    for (int e = blockIdx.x * blockDim.x + threadIdx.x; e < N_EDGES;
         e += gridDim.x * blockDim.x) {
        int p = atomicAdd(&g_cur[dstA[e]], 1);
        g_csr[p] = srcA[e];
    }
}

__global__ void bn_finalize_kernel(const float* __restrict__ gamma,
                                   const float* __restrict__ beta) {
    int t = threadIdx.x;
    if (t < D) {
        float mu  = g_sum[t]   * (1.0f / (float)N_NODES);
        float var = g_sumsq[t] * (1.0f / (float)N_NODES) - mu * mu;
        if (var < 0.0f) var = 0.0f;
        float inv = rsqrtf(var + BN_EPS);
        float sc  = gamma[t] * inv;
        g_scale[t] = sc;
        g_shift[t] = beta[t] - mu * sc;
        g_sum[t]   = 0.0f;
        g_sumsq[t] = 0.0f;
    }
}

// ---------------------------------------------------------------------------
// Aggregation: out = scale ⊙ (x_i + Σ_{j->i} x_j) + (1+deg)·shift   (MLP=8)
// ---------------------------------------------------------------------------
__global__ void __launch_bounds__(256)
aggregate_kernel(const float* __restrict__ xin, float* __restrict__ out) {
    int warp = threadIdx.x >> 5;
    int lane = threadIdx.x & 31;
    int node = blockIdx.x * 8 + warp;
    if (node >= N_NODES) return;
    int c0 = lane * 4;

    float4 a0 = *reinterpret_cast<const float4*>(&xin[(size_t)node * D + c0]);
    float4 a1 = make_float4(0.f, 0.f, 0.f, 0.f);
    float4 a2 = make_float4(0.f, 0.f, 0.f, 0.f);
    float4 a3 = make_float4(0.f, 0.f, 0.f, 0.f);
    int s = g_off[node], e = g_off[node + 1];
    int deg = e - s;

    for (int b = s; b < e; b += 32) {
        int m = e - b;
        if (m > 32) m = 32;
        int idx = (lane < m) ? g_csr[b + lane] : 0;
        int t = 0;
        for (; t + 8 <= m; t += 8) {
            int j0 = __shfl_sync(0xffffffffu, idx, t);
            int j1 = __shfl_sync(0xffffffffu, idx, t + 1);
            int j2 = __shfl_sync(0xffffffffu, idx, t + 2);
            int j3 = __shfl_sync(0xffffffffu, idx, t + 3);
            int j4 = __shfl_sync(0xffffffffu, idx, t + 4);
            int j5 = __shfl_sync(0xffffffffu, idx, t + 5);
            int j6 = __shfl_sync(0xffffffffu, idx, t + 6);
            int j7 = __shfl_sync(0xffffffffu, idx, t + 7);
            float4 v0 = *reinterpret_cast<const float4*>(&xin[(size_t)j0 * D + c0]);
            float4 v1 = *reinterpret_cast<const float4*>(&xin[(size_t)j1 * D + c0]);
            float4 v2 = *reinterpret_cast<const float4*>(&xin[(size_t)j2 * D + c0]);
            float4 v3 = *reinterpret_cast<const float4*>(&xin[(size_t)j3 * D + c0]);
            float4 v4 = *reinterpret_cast<const float4*>(&xin[(size_t)j4 * D + c0]);
            float4 v5 = *reinterpret_cast<const float4*>(&xin[(size_t)j5 * D + c0]);
            float4 v6 = *reinterpret_cast<const float4*>(&xin[(size_t)j6 * D + c0]);
            float4 v7 = *reinterpret_cast<const float4*>(&xin[(size_t)j7 * D + c0]);
            a0.x += v0.x + v4.x; a0.y += v0.y + v4.y;
            a0.z += v0.z + v4.z; a0.w += v0.w + v4.w;
            a1.x += v1.x + v5.x; a1.y += v1.y + v5.y;
            a1.z += v1.z + v5.z; a1.w += v1.w + v5.w;
            a2.x += v2.x + v6.x; a2.y += v2.y + v6.y;
            a2.z += v2.z + v6.z; a2.w += v2.w + v6.w;
            a3.x += v3.x + v7.x; a3.y += v3.y + v7.y;
            a3.z += v3.z + v7.z; a3.w += v3.w + v7.w;
        }
        for (; t + 4 <= m; t += 4) {
            int j0 = __shfl_sync(0xffffffffu, idx, t);
            int j1 = __shfl_sync(0xffffffffu, idx, t + 1);
            int j2 = __shfl_sync(0xffffffffu, idx, t + 2);
            int j3 = __shfl_sync(0xffffffffu, idx, t + 3);
            float4 v0 = *reinterpret_cast<const float4*>(&xin[(size_t)j0 * D + c0]);
            float4 v1 = *reinterpret_cast<const float4*>(&xin[(size_t)j1 * D + c0]);
            float4 v2 = *reinterpret_cast<const float4*>(&xin[(size_t)j2 * D + c0]);
            float4 v3 = *reinterpret_cast<const float4*>(&xin[(size_t)j3 * D + c0]);
            a0.x += v0.x; a0.y += v0.y; a0.z += v0.z; a0.w += v0.w;
            a1.x += v1.x; a1.y += v1.y; a1.z += v1.z; a1.w += v1.w;
            a2.x += v2.x; a2.y += v2.y; a2.z += v2.z; a2.w += v2.w;
            a3.x += v3.x; a3.y += v3.y; a3.z += v3.z; a3.w += v3.w;
        }
        for (; t < m; t++) {
            int j = __shfl_sync(0xffffffffu, idx, t);
            float4 v = *reinterpret_cast<const float4*>(&xin[(size_t)j * D + c0]);
            a0.x += v.x; a0.y += v.y; a0.z += v.z; a0.w += v.w;
        }
    }
    a0.x += a1.x + a2.x + a3.x;
    a0.y += a1.y + a2.y + a3.y;
    a0.z += a1.z + a2.z + a3.z;
    a0.w += a1.w + a2.w + a3.w;

    float4 sc = *reinterpret_cast<const float4*>(&g_scale[c0]);
    float4 sh = *reinterpret_cast<const float4*>(&g_shift[c0]);
    float dp1 = (float)(deg + 1);
    float4 o;
    o.x = sc.x * a0.x + dp1 * sh.x;
    o.y = sc.y * a0.y + dp1 * sh.y;
    o.z = sc.z * a0.z + dp1 * sh.z;
    o.w = sc.w * a0.w + dp1 * sh.w;
    __stcs(reinterpret_cast<float4*>(&out[(size_t)node * D + c0]), o);
}

// ---------------------------------------------------------------------------
// Fused layer MLP (FFMA2, 128x128 tile, 256 threads, 2 CTAs/SM):
//   C = relu(relu(A@W1+b1)@W2+b2) + BN stats; POOL=1 → pooled atomics.
// W stays in GLOBAL, read via __ldg (L1-resident: 64KB W << L1 after 70KB
// smem); smem holds only the A tile -> 2 resident CTAs overlap syncs/tails.
// 8 rows x 8 cols per thread (cols {2tx+32c}); {a,a} packed via mov.b64.
// ---------------------------------------------------------------------------
#define GT      256
#define AST2    132
#define SM_A    0                           // A: 128*132 = 16896 floats
#define SM_B1   (128 * AST2)
#define SM_B2   (SM_B1 + 128)
#define SM_SUM  (SM_B2 + 128)
#define SM_SQ   (SM_SUM + 128)
#define SM_TOT  ((SM_SQ + 128) * 4)         // ~69.6 KB

template <int POOL>
__global__ void __launch_bounds__(GT, 2)
fused_mlp(const float* __restrict__ A,
          const float* __restrict__ W1, const float* __restrict__ b1,
          const float* __restrict__ W2, const float* __restrict__ b2,
          float* __restrict__ Cout, const int* __restrict__ batch) {
    extern __shared__ float smem[];
    float* sA = smem + SM_A;

    const int tid  = threadIdx.x;
    const int row0 = blockIdx.x * 128;

    // A tile: 128 x 128 plain f32
    for (int i = tid; i < 128 * 32; i += GT) {
        int m  = i >> 5;
        int k4 = (i & 31) << 2;
        float4 v = make_float4(0.f, 0.f, 0.f, 0.f);
        if (row0 + m < N_NODES)
            v = __ldcs(reinterpret_cast<const float4*>(
                    &A[(size_t)(row0 + m) * D + k4]));
        *reinterpret_cast<float4*>(&sA[m * AST2 + k4]) = v;
    }
    if (tid < D) {
        smem[SM_B1 + tid]  = b1[tid];
        smem[SM_B2 + tid]  = b2[tid];
        smem[SM_SUM + tid] = 0.0f;
        smem[SM_SQ + tid]  = 0.0f;
    }
    __syncthreads();

    const int tx = tid & 15;           // col group: cols {2tx+32c}
    const int ty = tid >> 4;           // 16 row groups of 8 rows
    const int r0 = ty * 8;
    const float* aBase = &sA[r0 * AST2];

    const unsigned long long* W1p =
        reinterpret_cast<const unsigned long long*>(W1);
    const unsigned long long* W2p =
        reinterpret_cast<const unsigned long long*>(W2);
    const int colOff = tx;             // (2*tx)/2 in ull units

    unsigned long long acc[8][4];

    // ================= GEMM 1 (W1 via L1) =================
    #pragma unroll
    for (int r = 0; r < 8; r++)
        #pragma unroll
        for (int c = 0; c < 4; c++) acc[r][c] = 0ull;

    for (int k = 0; k < D; k += 2) {
        unsigned long long wv0[4], wv1[4];
        #pragma unroll
        for (int c = 0; c < 4; c++) {
            wv0[c] = __ldg(&W1p[(size_t)k * 64 + colOff + 16 * c]);
            wv1[c] = __ldg(&W1p[(size_t)(k + 1) * 64 + colOff + 16 * c]);
        }
        #pragma unroll
        for (int r = 0; r < 8; r++) {
            float2 a2v = *reinterpret_cast<const float2*>(
                aBase + r * AST2 + k);
            unsigned long long ax = pack2(a2v.x);
            unsigned long long ay = pack2(a2v.y);
            #pragma unroll
            for (int c = 0; c < 4; c++) {
                acc[r][c] = ffma2(ax, wv0[c], acc[r][c]);
                acc[r][c] = ffma2(ay, wv1[c], acc[r][c]);
            }
        }
    }
    __syncthreads();   // all reads of sA complete

    // h1 = relu(acc + b1) -> sA plain
    #pragma unroll
    for (int r = 0; r < 8; r++) {
        #pragma unroll
        for (int c = 0; c < 4; c++) {
            int n0 = 2 * tx + 32 * c;
            float lo, hi;
            unpack2(acc[r][c], lo, hi);
            lo = fmaxf(lo + smem[SM_B1 + n0], 0.0f);
            hi = fmaxf(hi + smem[SM_B1 + n0 + 1], 0.0f);
            *reinterpret_cast<float2*>(&sA[(r0 + r) * AST2 + n0]) =
                make_float2(lo, hi);
        }
    }
    __syncthreads();

    // ================= GEMM 2 (W2 via L1) =================
    #pragma unroll
    for (int r = 0; r < 8; r++)
        #pragma unroll
        for (int c = 0; c < 4; c++) acc[r][c] = 0ull;

    for (int k = 0; k < D; k += 2) {
        unsigned long long wv0[4], wv1[4];
        #pragma unroll
        for (int c = 0; c < 4; c++) {
            wv0[c] = __ldg(&W2p[(size_t)k * 64 + colOff + 16 * c]);
            wv1[c] = __ldg(&W2p[(size_t)(k + 1) * 64 + colOff + 16 * c]);
        }
        #pragma unroll
        for (int r = 0; r < 8; r++) {
            float2 a2v = *reinterpret_cast<const float2*>(
                aBase + r * AST2 + k);
            unsigned long long ax = pack2(a2v.x);
            unsigned long long ay = pack2(a2v.y);
            #pragma unroll
            for (int c = 0; c < 4; c++) {
                acc[r][c] = ffma2(ax, wv0[c], acc[r][c]);
                acc[r][c] = ffma2(ay, wv1[c], acc[r][c]);
            }
        }
    }

    // ---- epilogue: relu + b2; store or pool; BN stats ----
    float lsum[8], lsq[8];
    #pragma unroll
    for (int c = 0; c < 8; c++) { lsum[c] = 0.0f; lsq[c] = 0.0f; }

    #pragma unroll
    for (int r = 0; r < 8; r++) {
        int gr = row0 + r0 + r;
        if (gr >= N_NODES) break;
        int g = 0;
        if (POOL) {
            g = batch[gr];
            if (tx == 0) atomicAdd(&g_cnt[g], 1.0f);
        }
        #pragma unroll
        for (int c = 0; c < 4; c++) {
            int n0 = 2 * tx + 32 * c;
            float lo, hi;
            unpack2(acc[r][c], lo, hi);
            lo = fmaxf(lo + smem[SM_B2 + n0], 0.0f);
            hi = fmaxf(hi + smem[SM_B2 + n0 + 1], 0.0f);
            if (POOL) {
                atomicAdd(&g_pool[g * D + n0],     lo);
                atomicAdd(&g_pool[g * D + n0 + 1], hi);
            } else {
                *reinterpret_cast<float2*>(&Cout[(size_t)gr * D + n0]) =
                    make_float2(lo, hi);
            }
            lsum[2 * c]     += lo;
            lsum[2 * c + 1] += hi;
            lsq[2 * c]      += lo * lo;
            lsq[2 * c + 1]  += hi * hi;
        }
    }

    #pragma unroll
    for (int c = 0; c < 4; c++) {
        int n0 = 2 * tx + 32 * c;
        atomicAdd(&smem[SM_SUM + n0],     lsum[2 * c]);
        atomicAdd(&smem[SM_SUM + n0 + 1], lsum[2 * c + 1]);
        atomicAdd(&smem[SM_SQ + n0],      lsq[2 * c]);
        atomicAdd(&smem[SM_SQ + n0 + 1],  lsq[2 * c + 1]);
    }
    __syncthreads();
    if (tid < D) {
        atomicAdd(&g_sum[tid],   smem[SM_SUM + tid]);
        atomicAdd(&g_sumsq[tid], smem[SM_SQ + tid]);
    }
}

// ---------------------------------------------------------------------------
// MLP head
// ---------------------------------------------------------------------------
__global__ void head_kernel(const float* __restrict__ lin1w,
                            const float* __restrict__ lin1b,
                            const float* __restrict__ lin2w,
                            const float* __restrict__ lin2b,
                            float* __restrict__ out) {
    __shared__ float row[D];
    __shared__ float hid[D];
    int g = blockIdx.x;
    int t = threadIdx.x;
    float cnt = g_cnt[g];
    float p = 0.0f;
    if (cnt > 0.0f)
        p = g_scale[t] * g_pool[g * D + t] / cnt + g_shift[t];
    row[t] = p;
    __syncthreads();
    float a = lin1b[t];
    #pragma unroll 8
    for (int k = 0; k < D; k++) a += row[k] * lin1w[k * D + t];
    a = fmaxf(a, 0.0f);
    hid[t] = a;
    __syncthreads();
    if (t < N_CLASSES) {
        float o = lin2b[t];
        #pragma unroll 8
        for (int k = 0; k < D; k++) o += hid[k] * lin2w[k * N_CLASSES + t];
        out[g * N_CLASSES + t] = o;
    }
}

// ---------------------------------------------------------------------------
// Launcher
// ---------------------------------------------------------------------------
extern "C" void kernel_launch(void* const* d_in, const int* in_sizes, int n_in,
                              void* d_out, int out_size) {
    const float* x      = (const float*)d_in[0];
    const int*   ei     = (const int*)  d_in[1];
    const int*   batch  = (const int*)  d_in[2];
    const float* W1s    = (const float*)d_in[3];
    const float* b1s    = (const float*)d_in[4];
    const float* W2s    = (const float*)d_in[5];
    const float* b2s    = (const float*)d_in[6];
    const float* gammas = (const float*)d_in[7];
    const float* betas  = (const float*)d_in[8];
    const float* lin1w  = (const float*)d_in[9];
    const float* lin1b  = (const float*)d_in[10];
    const float* lin2w  = (const float*)d_in[11];
    const float* lin2b  = (const float*)d_in[12];
    float* out = (float*)d_out;

    const int* srcA = ei;
    const int* dstA = ei + N_EDGES;

    cudaFuncSetAttribute(fused_mlp<0>,
                         cudaFuncAttributeMaxDynamicSharedMemorySize, SM_TOT);
    cudaFuncSetAttribute(fused_mlp<1>,
                         cudaFuncAttributeMaxDynamicSharedMemorySize, SM_TOT);

    void *pA, *pB;
    cudaGetSymbolAddress(&pA, g_bufA);
    cudaGetSymbolAddress(&pB, g_bufB);
    float* bufs[2] = { (float*)pA, (float*)pB };

    const int AGG_BLOCKS  = (N_NODES + 7) / 8;            // 12500
    const int GEMM_BLOCKS = (N_NODES + 127) / 128;        // 782

    hist_kernel<<<2048, 256>>>(dstA);
    scan_kernel<<<1, 1024>>>();
    fill_kernel<<<2048, 256>>>(srcA, dstA);

    // ---- layer 0 ----
    float* t0 = bufs[0];
    aggregate_kernel<<<AGG_BLOCKS, 256>>>(x, t0);
    fused_mlp<0><<<GEMM_BLOCKS, GT, SM_TOT>>>(t0, W1s, b1s, W2s, b2s,
                                              t0, batch);
    bn_finalize_kernel<<<1, 128>>>(gammas, betas);

    // ---- layer 1 ----
    float* t1 = bufs[1];
    aggregate_kernel<<<AGG_BLOCKS, 256>>>(t0, t1);
    fused_mlp<0><<<GEMM_BLOCKS, GT, SM_TOT>>>(t1, W1s + D * D, b1s + D,
                                              W2s + D * D, b2s + D,
                                              t1, batch);
    bn_finalize_kernel<<<1, 128>>>(gammas + D, betas + D);

    // ---- layer 2 (pooled epilogue) ----
    aggregate_kernel<<<AGG_BLOCKS, 256>>>(t1, t0);
    fused_mlp<1><<<GEMM_BLOCKS, GT, SM_TOT>>>(t0, W1s + 2 * D * D,
                                              b1s + 2 * D,
                                              W2s + 2 * D * D, b2s + 2 * D,
                                              t0, batch);
    bn_finalize_kernel<<<1, 128>>>(gammas + 2 * D, betas + 2 * D);

    head_kernel<<<N_GRAPHS, 128>>>(lin1w, lin1b, lin2w, lin2b, out);
}

// round 16
// speedup vs baseline: 1.1250x; 1.1250x over previous
#include <cuda_runtime.h>
#include <cuda_fp16.h>
#include <stdint.h>

#define N_NODES   100000
#define N_EDGES   1600000
#define D         128
#define N_LAYERS  3
#define N_CLASSES 10
#define N_GRAPHS  512
#define BN_EPS    1e-5f

// ---------------------------------------------------------------------------
// Static device scratch (zero-init at load; kernels re-zero what they dirty)
// ---------------------------------------------------------------------------
__device__ __half g_hbufA[(size_t)N_NODES * D];   // 25.6 MB
__device__ __half g_hbufB[(size_t)N_NODES * D];   // 25.6 MB
__device__ int    g_deg[N_NODES];
__device__ int    g_off[N_NODES + 1];
__device__ int    g_cur[N_NODES];
__device__ int    g_csr[N_EDGES];
__device__ float  g_sum[D];
__device__ float  g_sumsq[D];
__device__ float  g_scale[D];
__device__ float  g_shift[D];
__device__ float  g_pool[N_GRAPHS * D];
__device__ float  g_cnt[N_GRAPHS];

// ---------------------------------------------------------------------------
// Packed f32x2 helpers
// ---------------------------------------------------------------------------
__device__ __forceinline__ unsigned long long ffma2(unsigned long long a,
                                                    unsigned long long b,
                                                    unsigned long long c) {
    unsigned long long d;
    asm("fma.rn.f32x2 %0, %1, %2, %3;" : "=l"(d) : "l"(a), "l"(b), "l"(c));
    return d;
}
__device__ __forceinline__ void unpack2(unsigned long long v, float& lo, float& hi) {
    unsigned int a, b;
    asm("mov.b64 {%0, %1}, %2;" : "=r"(a), "=r"(b) : "l"(v));
    lo = __uint_as_float(a);
    hi = __uint_as_float(b);
}
__device__ __forceinline__ unsigned long long pack2(float x) {
    unsigned long long r;
    unsigned int u = __float_as_uint(x);
    asm("mov.b64 %0, {%1, %1};" : "=l"(r) : "r"(u));
    return r;
}
__device__ __forceinline__ float4 h4_to_f4(uint2 u) {
    __half2 p0 = *reinterpret_cast<__half2*>(&u.x);
    __half2 p1 = *reinterpret_cast<__half2*>(&u.y);
    float2 f0 = __half22float2(p0);
    float2 f1 = __half22float2(p1);
    return make_float4(f0.x, f0.y, f1.x, f1.y);
}
__device__ __forceinline__ uint2 f4_to_h4(float4 v) {
    __half2 p0 = __floats2half2_rn(v.x, v.y);
    __half2 p1 = __floats2half2_rn(v.z, v.w);
    uint2 u;
    u.x = *reinterpret_cast<unsigned*>(&p0);
    u.y = *reinterpret_cast<unsigned*>(&p1);
    return u;
}

// ---------------------------------------------------------------------------
// CSR build (g_deg zero on entry; scan self-cleans it)
// ---------------------------------------------------------------------------
__global__ void hist_kernel(const int* __restrict__ dstA) {
    for (int e = blockIdx.x * blockDim.x + threadIdx.x; e < N_EDGES;
         e += gridDim.x * blockDim.x)
        atomicAdd(&g_deg[dstA[e]], 1);
}

__global__ void scan_kernel() {
    const int T = 1024;
    const int chunk = (N_NODES + T - 1) / T;
    int tid = threadIdx.x;
    int lo = tid * chunk, hi = lo + chunk;
    if (hi > N_NODES) hi = N_NODES;
    if (lo > N_NODES) lo = N_NODES;
    int s = 0;
    for (int i = lo; i < hi; i++) s += g_deg[i];
    __shared__ int sm[T];
    sm[tid] = s;
    __syncthreads();
    for (int off = 1; off < T; off <<= 1) {
        int v = (tid >= off) ? sm[tid - off] : 0;
        __syncthreads();
        sm[tid] += v;
        __syncthreads();
    }
    int run = (tid == 0) ? 0 : sm[tid - 1];
    for (int i = lo; i < hi; i++) {
        int d = g_deg[i];
        g_off[i] = run;
        g_cur[i] = run;
        run += d;
        g_deg[i] = 0;
    }
    if (tid == T - 1) g_off[N_NODES] = run;
    if (tid < D) {
        g_scale[tid] = 1.0f;
        g_shift[tid] = 0.0f;
        g_sum[tid]   = 0.0f;
        g_sumsq[tid] = 0.0f;
    }
    for (int i = tid; i < N_GRAPHS * D; i += T) g_pool[i] = 0.0f;
    for (int i = tid; i < N_GRAPHS; i += T)     g_cnt[i]  = 0.0f;
}

__global__ void fill_kernel(const int* __restrict__ srcA,
                            const int* __restrict__ dstA) {
    for (int e = blockIdx.x * blockDim.x + threadIdx.x; e < N_EDGES;
         e += gridDim.x * blockDim.x) {
        int p = atomicAdd(&g_cur[dstA[e]], 1);
        g_csr[p] = srcA[e];
    }
}

__global__ void bn_finalize_kernel(const float* __restrict__ gamma,
                                   const float* __restrict__ beta) {
    int t = threadIdx.x;
    if (t < D) {
        float mu  = g_sum[t]   * (1.0f / (float)N_NODES);
        float var = g_sumsq[t] * (1.0f / (float)N_NODES) - mu * mu;
        if (var < 0.0f) var = 0.0f;
        float inv = rsqrtf(var + BN_EPS);
        float sc  = gamma[t] * inv;
        g_scale[t] = sc;
        g_shift[t] = beta[t] - mu * sc;
        g_sum[t]   = 0.0f;
        g_sumsq[t] = 0.0f;
    }
}

// x (fp32) -> fp16 buffer
__global__ void convert_x_kernel(const float* __restrict__ x,
                                 __half* __restrict__ out) {
    size_t n = (size_t)N_NODES * D;
    for (size_t i = (blockIdx.x * blockDim.x + threadIdx.x) * 4; i < n;
         i += (size_t)gridDim.x * blockDim.x * 4) {
        float4 v = *reinterpret_cast<const float4*>(&x[i]);
        *reinterpret_cast<uint2*>(&out[i]) = f4_to_h4(v);
    }
}

// ---------------------------------------------------------------------------
// Aggregation (fp16 in/out, fp32 accumulate):
//   out = scale ⊙ (x_i + Σ_{j->i} x_j) + (1+deg)·shift       (MLP=8)
// ---------------------------------------------------------------------------
__global__ void __launch_bounds__(256)
aggregate_kernel(const __half* __restrict__ xin, __half* __restrict__ out) {
    int warp = threadIdx.x >> 5;
    int lane = threadIdx.x & 31;
    int node = blockIdx.x * 8 + warp;
    if (node >= N_NODES) return;
    int c0 = lane * 4;

    float4 a0 = h4_to_f4(*reinterpret_cast<const uint2*>(
        &xin[(size_t)node * D + c0]));
    float4 a1 = make_float4(0.f, 0.f, 0.f, 0.f);
    float4 a2 = make_float4(0.f, 0.f, 0.f, 0.f);
    float4 a3 = make_float4(0.f, 0.f, 0.f, 0.f);
    int s = g_off[node], e = g_off[node + 1];
    int deg = e - s;

    for (int b = s; b < e; b += 32) {
        int m = e - b;
        if (m > 32) m = 32;
        int idx = (lane < m) ? g_csr[b + lane] : 0;
        int t = 0;
        for (; t + 8 <= m; t += 8) {
            int j0 = __shfl_sync(0xffffffffu, idx, t);
            int j1 = __shfl_sync(0xffffffffu, idx, t + 1);
            int j2 = __shfl_sync(0xffffffffu, idx, t + 2);
            int j3 = __shfl_sync(0xffffffffu, idx, t + 3);
            int j4 = __shfl_sync(0xffffffffu, idx, t + 4);
            int j5 = __shfl_sync(0xffffffffu, idx, t + 5);
            int j6 = __shfl_sync(0xffffffffu, idx, t + 6);
            int j7 = __shfl_sync(0xffffffffu, idx, t + 7);
            uint2 u0 = *reinterpret_cast<const uint2*>(&xin[(size_t)j0 * D + c0]);
            uint2 u1 = *reinterpret_cast<const uint2*>(&xin[(size_t)j1 * D + c0]);
            uint2 u2 = *reinterpret_cast<const uint2*>(&xin[(size_t)j2 * D + c0]);
            uint2 u3 = *reinterpret_cast<const uint2*>(&xin[(size_t)j3 * D + c0]);
            uint2 u4 = *reinterpret_cast<const uint2*>(&xin[(size_t)j4 * D + c0]);
            uint2 u5 = *reinterpret_cast<const uint2*>(&xin[(size_t)j5 * D + c0]);
            uint2 u6 = *reinterpret_cast<const uint2*>(&xin[(size_t)j6 * D + c0]);
            uint2 u7 = *reinterpret_cast<const uint2*>(&xin[(size_t)j7 * D + c0]);
            float4 v0 = h4_to_f4(u0), v1 = h4_to_f4(u1);
            float4 v2 = h4_to_f4(u2), v3 = h4_to_f4(u3);
            float4 v4 = h4_to_f4(u4), v5 = h4_to_f4(u5);
            float4 v6 = h4_to_f4(u6), v7 = h4_to_f4(u7);
            a0.x += v0.x + v4.x; a0.y += v0.y + v4.y;
            a0.z += v0.z + v4.z; a0.w += v0.w + v4.w;
            a1.x += v1.x + v5.x; a1.y += v1.y + v5.y;
            a1.z += v1.z + v5.z; a1.w += v1.w + v5.w;
            a2.x += v2.x + v6.x; a2.y += v2.y + v6.y;
            a2.z += v2.z + v6.z; a2.w += v2.w + v6.w;
            a3.x += v3.x + v7.x; a3.y += v3.y + v7.y;
            a3.z += v3.z + v7.z; a3.w += v3.w + v7.w;
        }
        for (; t + 4 <= m; t += 4) {
            int j0 = __shfl_sync(0xffffffffu, idx, t);
            int j1 = __shfl_sync(0xffffffffu, idx, t + 1);
            int j2 = __shfl_sync(0xffffffffu, idx, t + 2);
            int j3 = __shfl_sync(0xffffffffu, idx, t + 3);
            float4 v0 = h4_to_f4(*reinterpret_cast<const uint2*>(&xin[(size_t)j0 * D + c0]));
            float4 v1 = h4_to_f4(*reinterpret_cast<const uint2*>(&xin[(size_t)j1 * D + c0]));
            float4 v2 = h4_to_f4(*reinterpret_cast<const uint2*>(&xin[(size_t)j2 * D + c0]));
            float4 v3 = h4_to_f4(*reinterpret_cast<const uint2*>(&xin[(size_t)j3 * D + c0]));
            a0.x += v0.x; a0.y += v0.y; a0.z += v0.z; a0.w += v0.w;
            a1.x += v1.x; a1.y += v1.y; a1.z += v1.z; a1.w += v1.w;
            a2.x += v2.x; a2.y += v2.y; a2.z += v2.z; a2.w += v2.w;
            a3.x += v3.x; a3.y += v3.y; a3.z += v3.z; a3.w += v3.w;
        }
        for (; t < m; t++) {
            int j = __shfl_sync(0xffffffffu, idx, t);
            float4 v = h4_to_f4(*reinterpret_cast<const uint2*>(&xin[(size_t)j * D + c0]));
            a0.x += v.x; a0.y += v.y; a0.z += v.z; a0.w += v.w;
        }
    }
    a0.x += a1.x + a2.x + a3.x;
    a0.y += a1.y + a2.y + a3.y;
    a0.z += a1.z + a2.z + a3.z;
    a0.w += a1.w + a2.w + a3.w;

    float4 sc = *reinterpret_cast<const float4*>(&g_scale[c0]);
    float4 sh = *reinterpret_cast<const float4*>(&g_shift[c0]);
    float dp1 = (float)(deg + 1);
    float4 o;
    o.x = sc.x * a0.x + dp1 * sh.x;
    o.y = sc.y * a0.y + dp1 * sh.y;
    o.z = sc.z * a0.z + dp1 * sh.z;
    o.w = sc.w * a0.w + dp1 * sh.w;
    uint2 st = f4_to_h4(o);
    __stcs(reinterpret_cast<uint2*>(&out[(size_t)node * D + c0]), st);
}

// ---------------------------------------------------------------------------
// Fused layer MLP (FFMA2, 256x128 tile, 512 threads, 8 rows x 8 cols/thread):
//   C = relu(relu(A@W1+b1)@W2+b2) + BN stats; POOL=1 → pooled atomics.
// A in fp16 (converted to fp32 smem tile); GEMMs in fp32 FFMA2; output fp16.
// In-place safe (Cout may equal A): CTA touches only its own 256 rows.
// ---------------------------------------------------------------------------
#define GT      512
#define AST2    132
#define SM_W    0
#define SM_A    16384                       // W: 128*128
#define SM_B1   (16384 + 256 * AST2)        // A: 256*132 = 33792
#define SM_B2   (SM_B1 + 128)
#define SM_SUM  (SM_B2 + 128)
#define SM_SQ   (SM_SUM + 128)
#define SM_TOT  ((SM_SQ + 128) * 4)

template <int POOL>
__global__ void __launch_bounds__(GT, 1)
fused_mlp(const __half* __restrict__ A,
          const float* __restrict__ W1, const float* __restrict__ b1,
          const float* __restrict__ W2, const float* __restrict__ b2,
          __half* __restrict__ Cout, const int* __restrict__ batch) {
    extern __shared__ float smem[];
    float* sW = smem + SM_W;
    float* sA = smem + SM_A;

    const int tid  = threadIdx.x;
    const int row0 = blockIdx.x * 256;

    #pragma unroll
    for (int i = tid * 4; i < D * D; i += GT * 4)
        *reinterpret_cast<float4*>(&sW[i]) =
            *reinterpret_cast<const float4*>(&W1[i]);

    // A tile: 256 x 128, fp16 -> fp32
    for (int i = tid; i < 256 * 32; i += GT) {
        int m  = i >> 5;
        int k4 = (i & 31) << 2;
        float4 v = make_float4(0.f, 0.f, 0.f, 0.f);
        if (row0 + m < N_NODES) {
            uint2 u = __ldcs(reinterpret_cast<const uint2*>(
                &A[(size_t)(row0 + m) * D + k4]));
            v = h4_to_f4(u);
        }
        *reinterpret_cast<float4*>(&sA[m * AST2 + k4]) = v;
    }
    if (tid < D) {
        smem[SM_B1 + tid]  = b1[tid];
        smem[SM_B2 + tid]  = b2[tid];
        smem[SM_SUM + tid] = 0.0f;
        smem[SM_SQ + tid]  = 0.0f;
    }
    __syncthreads();

    const int tx = tid & 15;           // col group: cols {2tx+32c}
    const int ty = tid >> 4;           // 32 row groups of 8 rows
    const int r0 = ty * 8;
    const float* aBase = &sA[r0 * AST2];

    unsigned long long acc[8][4];

    // ================= GEMM 1 =================
    #pragma unroll
    for (int r = 0; r < 8; r++)
        #pragma unroll
        for (int c = 0; c < 4; c++) acc[r][c] = 0ull;

    for (int k = 0; k < D; k += 2) {
        unsigned long long wv0[4], wv1[4];
        #pragma unroll
        for (int c = 0; c < 4; c++) {
            wv0[c] = *reinterpret_cast<const unsigned long long*>(
                &sW[k * D + 2 * tx + 32 * c]);
            wv1[c] = *reinterpret_cast<const unsigned long long*>(
                &sW[(k + 1) * D + 2 * tx + 32 * c]);
        }
        #pragma unroll
        for (int r = 0; r < 8; r++) {
            float2 a2v = *reinterpret_cast<const float2*>(
                aBase + r * AST2 + k);
            unsigned long long ax = pack2(a2v.x);
            unsigned long long ay = pack2(a2v.y);
            #pragma unroll
            for (int c = 0; c < 4; c++) {
                acc[r][c] = ffma2(ax, wv0[c], acc[r][c]);
                acc[r][c] = ffma2(ay, wv1[c], acc[r][c]);
            }
        }
    }
    __syncthreads();   // all reads of sA/sW complete

    // h1 = relu(acc + b1) -> sA plain; W2 -> sW
    #pragma unroll
    for (int r = 0; r < 8; r++) {
        #pragma unroll
        for (int c = 0; c < 4; c++) {
            int n0 = 2 * tx + 32 * c;
            float lo, hi;
            unpack2(acc[r][c], lo, hi);
            lo = fmaxf(lo + smem[SM_B1 + n0], 0.0f);
            hi = fmaxf(hi + smem[SM_B1 + n0 + 1], 0.0f);
            *reinterpret_cast<float2*>(&sA[(r0 + r) * AST2 + n0]) =
                make_float2(lo, hi);
        }
    }
    #pragma unroll
    for (int i = tid * 4; i < D * D; i += GT * 4)
        *reinterpret_cast<float4*>(&sW[i]) =
            *reinterpret_cast<const float4*>(&W2[i]);
    __syncthreads();

    // ================= GEMM 2 =================
    #pragma unroll
    for (int r = 0; r < 8; r++)
        #pragma unroll
        for (int c = 0; c < 4; c++) acc[r][c] = 0ull;

    for (int k = 0; k < D; k += 2) {
        unsigned long long wv0[4], wv1[4];
        #pragma unroll
        for (int c = 0; c < 4; c++) {
            wv0[c] = *reinterpret_cast<const unsigned long long*>(
                &sW[k * D + 2 * tx + 32 * c]);
            wv1[c] = *reinterpret_cast<const unsigned long long*>(
                &sW[(k + 1) * D + 2 * tx + 32 * c]);
        }
        #pragma unroll
        for (int r = 0; r < 8; r++) {
            float2 a2v = *reinterpret_cast<const float2*>(
                aBase + r * AST2 + k);
            unsigned long long ax = pack2(a2v.x);
            unsigned long long ay = pack2(a2v.y);
            #pragma unroll
            for (int c = 0; c < 4; c++) {
                acc[r][c] = ffma2(ax, wv0[c], acc[r][c]);
                acc[r][c] = ffma2(ay, wv1[c], acc[r][c]);
            }
        }
    }

    // ---- epilogue: relu + b2; store fp16 or pool; BN stats (fp32) ----
    float lsum[8], lsq[8];
    #pragma unroll
    for (int c = 0; c < 8; c++) { lsum[c] = 0.0f; lsq[c] = 0.0f; }

    #pragma unroll
    for (int r = 0; r < 8; r++) {
        int gr = row0 + r0 + r;
        if (gr >= N_NODES) break;
        int g = 0;
        if (POOL) {
            g = batch[gr];
            if (tx == 0) atomicAdd(&g_cnt[g], 1.0f);
        }
        #pragma unroll
        for (int c = 0; c < 4; c++) {
            int n0 = 2 * tx + 32 * c;
            float lo, hi;
            unpack2(acc[r][c], lo, hi);
            lo = fmaxf(lo + smem[SM_B2 + n0], 0.0f);
            hi = fmaxf(hi + smem[SM_B2 + n0 + 1], 0.0f);
            if (POOL) {
                atomicAdd(&g_pool[g * D + n0],     lo);
                atomicAdd(&g_pool[g * D + n0 + 1], hi);
            } else {
                __half2 h = __floats2half2_rn(lo, hi);
                *reinterpret_cast<unsigned*>(&Cout[(size_t)gr * D + n0]) =
                    *reinterpret_cast<unsigned*>(&h);
            }
            lsum[2 * c]     += lo;
            lsum[2 * c + 1] += hi;
            lsq[2 * c]      += lo * lo;
            lsq[2 * c + 1]  += hi * hi;
        }
    }

    #pragma unroll
    for (int c = 0; c < 4; c++) {
        int n0 = 2 * tx + 32 * c;
        atomicAdd(&smem[SM_SUM + n0],     lsum[2 * c]);
        atomicAdd(&smem[SM_SUM + n0 + 1], lsum[2 * c + 1]);
        atomicAdd(&smem[SM_SQ + n0],      lsq[2 * c]);
        atomicAdd(&smem[SM_SQ + n0 + 1],  lsq[2 * c + 1]);
    }
    __syncthreads();
    if (tid < D) {
        atomicAdd(&g_sum[tid],   smem[SM_SUM + tid]);
        atomicAdd(&g_sumsq[tid], smem[SM_SQ + tid]);
    }
}

// ---------------------------------------------------------------------------
// MLP head
// ---------------------------------------------------------------------------
__global__ void head_kernel(const float* __restrict__ lin1w,
                            const float* __restrict__ lin1b,
                            const float* __restrict__ lin2w,
                            const float* __restrict__ lin2b,
                            float* __restrict__ out) {
    __shared__ float row[D];
    __shared__ float hid[D];
    int g = blockIdx.x;
    int t = threadIdx.x;
    float cnt = g_cnt[g];
    float p = 0.0f;
    if (cnt > 0.0f)
        p = g_scale[t] * g_pool[g * D + t] / cnt + g_shift[t];
    row[t] = p;
    __syncthreads();
    float a = lin1b[t];
    #pragma unroll 8
    for (int k = 0; k < D; k++) a += row[k] * lin1w[k * D + t];
    a = fmaxf(a, 0.0f);
    hid[t] = a;
    __syncthreads();
    if (t < N_CLASSES) {
        float o = lin2b[t];
        #pragma unroll 8
        for (int k = 0; k < D; k++) o += hid[k] * lin2w[k * N_CLASSES + t];
        out[g * N_CLASSES + t] = o;
    }
}

// ---------------------------------------------------------------------------
// Launcher
// ---------------------------------------------------------------------------
extern "C" void kernel_launch(void* const* d_in, const int* in_sizes, int n_in,
                              void* d_out, int out_size) {
    const float* x      = (const float*)d_in[0];
    const int*   ei     = (const int*)  d_in[1];
    const int*   batch  = (const int*)  d_in[2];
    const float* W1s    = (const float*)d_in[3];
    const float* b1s    = (const float*)d_in[4];
    const float* W2s    = (const float*)d_in[5];
    const float* b2s    = (const float*)d_in[6];
    const float* gammas = (const float*)d_in[7];
    const float* betas  = (const float*)d_in[8];
    const float* lin1w  = (const float*)d_in[9];
    const float* lin1b  = (const float*)d_in[10];
    const float* lin2w  = (const float*)d_in[11];
    const float* lin2b  = (const float*)d_in[12];
    float* out = (float*)d_out;

    const int* srcA = ei;
    const int* dstA = ei + N_EDGES;

    cudaFuncSetAttribute(fused_mlp<0>,
                         cudaFuncAttributeMaxDynamicSharedMemorySize, SM_TOT);
    cudaFuncSetAttribute(fused_mlp<1>,
                         cudaFuncAttributeMaxDynamicSharedMemorySize, SM_TOT);

    void *pA, *pB;
    cudaGetSymbolAddress(&pA, g_hbufA);
    cudaGetSymbolAddress(&pB, g_hbufB);
    __half* H0 = (__half*)pA;
    __half* H1 = (__half*)pB;

    const int AGG_BLOCKS  = (N_NODES + 7) / 8;            // 12500
    const int GEMM_BLOCKS = (N_NODES + 255) / 256;        // 391

    hist_kernel<<<2048, 256>>>(dstA);
    scan_kernel<<<1, 1024>>>();
    fill_kernel<<<2048, 256>>>(srcA, dstA);
    convert_x_kernel<<<2048, 256>>>(x, H0);

    // ---- layer 0 ----
    aggregate_kernel<<<AGG_BLOCKS, 256>>>(H0, H1);
    fused_mlp<0><<<GEMM_BLOCKS, GT, SM_TOT>>>(H1, W1s, b1s, W2s, b2s,
                                              H1, batch);         // in-place
    bn_finalize_kernel<<<1, 128>>>(gammas, betas);

    // ---- layer 1 ----
    aggregate_kernel<<<AGG_BLOCKS, 256>>>(H1, H0);
    fused_mlp<0><<<GEMM_BLOCKS, GT, SM_TOT>>>(H0, W1s + D * D, b1s + D,
                                              W2s + D * D, b2s + D,
                                              H0, batch);         // in-place
    bn_finalize_kernel<<<1, 128>>>(gammas + D, betas + D);

    // ---- layer 2 (pooled epilogue, no feature store) ----
    aggregate_kernel<<<AGG_BLOCKS, 256>>>(H0, H1);
    fused_mlp<1><<<GEMM_BLOCKS, GT, SM_TOT>>>(H1, W1s + 2 * D * D,
                                              b1s + 2 * D,
                                              W2s + 2 * D * D, b2s + 2 * D,
                                              H1, batch);
    bn_finalize_kernel<<<1, 128>>>(gammas + 2 * D, betas + 2 * D);

    head_kernel<<<N_GRAPHS, 128>>>(lin1w, lin1b, lin2w, lin2b, out);
}